// round 16
// baseline (speedup 1.0000x reference)
#include <cuda_runtime.h>
#include <cuda_fp16.h>
#include <cstdint>
#include <cstddef>

#define TS 2048
#define CE 512
#define DINL __device__ __forceinline__

// ---------------- scratch (bytes) ----------------
constexpr size_t B_ROWC = (size_t)8192 * 512 * 2;
constexpr size_t B_FF   = (size_t)8192 * 2048 * 2;
constexpr size_t B_QKV  = (size_t)32 * 2048 * 64 * 2;
constexpr size_t B_COL  = (size_t)32 * 2048 * 4;
constexpr size_t O_H    = 0;
constexpr size_t O_H2   = O_H   + B_ROWC;
constexpr size_t O_AO   = O_H2  + B_ROWC;
constexpr size_t O_FF   = O_AO  + B_ROWC;
constexpr size_t O_Q    = O_FF  + B_FF;
constexpr size_t O_K    = O_Q   + B_QKV;
constexpr size_t O_VT   = O_K   + B_QKV;
constexpr size_t O_WQKV = O_VT  + B_QKV;
constexpr size_t O_WOT  = O_WQKV + (size_t)1536*512*2;
constexpr size_t O_W1T  = O_WOT  + (size_t)512*512*2;
constexpr size_t O_W2T  = O_W1T  + (size_t)2048*512*2;
constexpr size_t O_L    = O_W2T  + (size_t)512*2048*2;
constexpr size_t O_X2   = O_L   + B_COL;
constexpr size_t O_PS   = O_X2  + (size_t)8192*512*4;          // psum [32][32][2048] f32
constexpr size_t SZ_ALL = O_PS  + (size_t)32*32*2048*4;

__device__ __align__(128) unsigned char g_s[SZ_ALL];

// ---------------- helpers ----------------
DINL uint32_t smem_u32(const void* p) {
    uint32_t a;
    asm("{ .reg .u64 t; cvta.to.shared.u64 t, %1; cvt.u32.u64 %0, t; }" : "=r"(a) : "l"(p));
    return a;
}
DINL uint32_t sw128(uint32_t off) { return off ^ ((off >> 3) & 0x70); }

DINL void cp16(uint32_t s, const void* g) {
    asm volatile("cp.async.cg.shared.global [%0], [%1], 16;" :: "r"(s), "l"(g));
}
#define CP_COMMIT() asm volatile("cp.async.commit_group;" ::: "memory")
template<int N> DINL void cp_wait() {
    asm volatile("cp.async.wait_group %0;" :: "n"(N) : "memory");
}

DINL void ldsm4(uint32_t* r, uint32_t a) {
    asm volatile("ldmatrix.sync.aligned.m8n8.x4.shared.b16 {%0,%1,%2,%3}, [%4];"
        : "=r"(r[0]), "=r"(r[1]), "=r"(r[2]), "=r"(r[3]) : "r"(a));
}
DINL void mma16816(float* d, const uint32_t* a, const uint32_t* b) {
    asm volatile("mma.sync.aligned.m16n8k16.row.col.f32.f16.f16.f32 "
        "{%0,%1,%2,%3},{%4,%5,%6,%7},{%8,%9},{%0,%1,%2,%3};"
        : "+f"(d[0]), "+f"(d[1]), "+f"(d[2]), "+f"(d[3])
        : "r"(a[0]), "r"(a[1]), "r"(a[2]), "r"(a[3]), "r"(b[0]), "r"(b[1]));
}
DINL uint32_t pack2(float a, float b) {
    union { __half2 h; uint32_t u; } cv;
    cv.h = __floats2half2_rn(a, b);
    return cv.u;
}
// async tile copy: NR rows x 64 halves (128B rows), SW128 swizzled; NTH threads
template<int NR, int NTH>
DINL void ld_tile_cpN(const __half* __restrict__ g, int ldh, uint32_t smp, int tid) {
    #pragma unroll
    for (int p = 0; p < NR * 8 / NTH; p++) {
        int u = tid + p * NTH, r = u >> 3, cc = u & 7;
        cp16(smp + sw128((uint32_t)(r << 7) + (cc << 4)),
             g + (size_t)r * ldh + (cc << 3));
    }
}
template<int NR>
DINL void ld_tile_cp(const __half* __restrict__ g, int ldh, uint32_t smp, int tid) {
    ld_tile_cpN<NR, 256>(g, ldh, smp, tid);
}
DINL void ldA(uint32_t buf, int lane, int m0, int ks, uint32_t a[4][4]) {
    int row = m0 + (lane & 15);
    uint32_t koff = (uint32_t)(ks << 5) + ((lane & 16) ? 16u : 0u);
    #pragma unroll
    for (int mt = 0; mt < 4; mt++)
        ldsm4(a[mt], buf + sw128((uint32_t)((row + mt * 16) << 7) + koff));
}
DINL void ldB16(uint32_t buf, int lane, int n0, int ks, uint32_t b[4]) {
    int row = n0 + (lane & 7) + ((lane & 16) >> 1);
    uint32_t koff = (uint32_t)(ks << 5) + ((lane & 8) << 1);
    ldsm4(b, buf + sw128((uint32_t)(row << 7) + koff));
}
// 64-K chunk (warp tile 64x32, 8 warps)
DINL void mma_chunk(uint32_t abuf, uint32_t bbuf, int lane, int wm, int wn, float acc[4][4][4]) {
    #pragma unroll
    for (int ks = 0; ks < 4; ks++) {
        uint32_t a[4][4], b[2][4];
        ldA(abuf, lane, wm * 64, ks, a);
        ldB16(bbuf, lane, wn * 32, ks, b[0]);
        ldB16(bbuf, lane, wn * 32 + 16, ks, b[1]);
        #pragma unroll
        for (int mt = 0; mt < 4; mt++)
            #pragma unroll
            for (int nt = 0; nt < 4; nt++)
                mma16816(acc[mt][nt], a[mt], &b[nt >> 1][(nt & 1) * 2]);
    }
}

// ---------------- LayerNorm fp32 -> fp16 ----------------
__global__ __launch_bounds__(256) void ln_h(
    const float* __restrict__ x, const float* __restrict__ g,
    const float* __restrict__ be, __half* __restrict__ o)
{
    const int row = blockIdx.x, t = threadIdx.x;
    const float* xr = x + (size_t)row * CE;
    float2 ab = *reinterpret_cast<const float2*>(xr + 2 * t);
    float s = ab.x + ab.y, sq = ab.x * ab.x + ab.y * ab.y;
    #pragma unroll
    for (int off = 16; off; off >>= 1) {
        s  += __shfl_xor_sync(~0u, s, off);
        sq += __shfl_xor_sync(~0u, sq, off);
    }
    __shared__ float sh[16];
    if ((t & 31) == 0) { sh[t >> 5] = s; sh[8 + (t >> 5)] = sq; }
    __syncthreads();
    if (t == 0) {
        float S = 0, Q = 0;
        #pragma unroll
        for (int i = 0; i < 8; i++) { S += sh[i]; Q += sh[8 + i]; }
        sh[0] = S; sh[8] = Q;
    }
    __syncthreads();
    float mu = sh[0] * (1.f / 512), var = sh[8] * (1.f / 512) - mu * mu;
    float inv = rsqrtf(var + 1e-5f);
    float o0 = (ab.x - mu) * inv * g[2 * t] + be[2 * t];
    float o1 = (ab.y - mu) * inv * g[2 * t + 1] + be[2 * t + 1];
    *reinterpret_cast<__half2*>(o + (size_t)row * CE + 2 * t) = __floats2half2_rn(o0, o1);
}

// ---------------- weight prep ----------------
__global__ void packqkv(const float* __restrict__ Wq, const float* __restrict__ Wk,
                        const float* __restrict__ Wv, __half* __restrict__ wt)
{
    __shared__ float tl[32][33];
    int c0 = blockIdx.x << 5, d0 = blockIdx.y << 5, z = blockIdx.z;
    int which = z >> 3, h = z & 7;
    const float* W = which == 0 ? Wq : (which == 1 ? Wk : Wv);
    // q scale: 512^-0.5 * log2(e)  (scores use exp2)
    float sc = which == 0 ? 0.04419417382415922f * 1.4426950408889634f : 1.f;
    tl[threadIdx.y][threadIdx.x] =
        W[((size_t)h * 512 + c0 + threadIdx.y) * 64 + d0 + threadIdx.x] * sc;
    __syncthreads();
    wt[((size_t)(which * 512 + h * 64 + d0 + threadIdx.y)) * 512 + c0 + threadIdx.x] =
        __float2half(tl[threadIdx.x][threadIdx.y]);
}
__global__ void tr_all(const float* __restrict__ Wo, const float* __restrict__ W1,
                       const float* __restrict__ W2, __half* __restrict__ wot,
                       __half* __restrict__ w1t, __half* __restrict__ w2t)
{
    __shared__ float tl[32][33];
    int bid = blockIdx.x;
    const float* in; __half* out; int K, N, tx_, ty_;
    if (bid < 256)       { in = Wo; out = wot; K = 512;  N = 512;  bid -= 0;    tx_ = bid & 15; ty_ = bid >> 4; }
    else if (bid < 1280) { in = W1; out = w1t; K = 512;  N = 2048; bid -= 256;  tx_ = bid & 63; ty_ = bid >> 6; }
    else                 { in = W2; out = w2t; K = 2048; N = 512;  bid -= 1280; tx_ = bid & 15; ty_ = bid >> 4; }
    int n0 = tx_ << 5, k0 = ty_ << 5;
    tl[threadIdx.y][threadIdx.x] = in[(size_t)(k0 + threadIdx.y) * N + n0 + threadIdx.x];
    __syncthreads();
    out[(size_t)(n0 + threadIdx.y) * K + k0 + threadIdx.x] = __float2half(tl[threadIdx.x][threadIdx.y]);
}

// ---------------- GEMM (cp.async 3-stage 64-K chunks, 2 CTAs/SM) ------------
template<int MODE>
__global__ __launch_bounds__(256, 2) void gemm_mma(
    const __half* __restrict__ A, const __half* __restrict__ B, int K,
    const float* __restrict__ bias, const float* __restrict__ res,
    float* __restrict__ outf, __half* __restrict__ outh,
    __half* __restrict__ oq, __half* __restrict__ ok2, __half* __restrict__ ov)
{
    extern __shared__ __align__(1024) char sm[];
    const uint32_t sA = smem_u32(sm);
    const uint32_t sB = sA + 49152;
    const int tid = threadIdx.x, lane = tid & 31, w = tid >> 5;
    const int wm = w & 1, wn = w >> 1;
    const int m0 = blockIdx.y << 7, n0 = blockIdx.x << 7;
    const __half* Ab = A + (size_t)m0 * K;
    const __half* Bb = B + (size_t)n0 * K;
    float acc[4][4][4];
    #pragma unroll
    for (int i = 0; i < 4; i++)
        #pragma unroll
        for (int j = 0; j < 4; j++)
            #pragma unroll
            for (int e = 0; e < 4; e++) acc[i][j][e] = 0.f;

    const int nc = K >> 6;
    ld_tile_cp<128>(Ab, K, sA, tid);
    ld_tile_cp<128>(Bb, K, sB, tid);
    CP_COMMIT();
    if (nc > 1) {
        ld_tile_cp<128>(Ab + 64, K, sA + 16384, tid);
        ld_tile_cp<128>(Bb + 64, K, sB + 16384, tid);
        CP_COMMIT();
    }
    for (int c = 0; c < nc; c++) {
        if (c + 1 < nc) cp_wait<1>(); else cp_wait<0>();
        __syncthreads();
        if (c + 2 < nc) {
            const uint32_t st = (uint32_t)((c + 2) % 3) << 14;
            ld_tile_cp<128>(Ab + ((c + 2) << 6), K, sA + st, tid);
            ld_tile_cp<128>(Bb + ((c + 2) << 6), K, sB + st, tid);
            CP_COMMIT();
        }
        const uint32_t cur = (uint32_t)(c % 3) << 14;
        mma_chunk(sA + cur, sB + cur, lane, wm, wn, acc);
    }
    const int gm = lane >> 2, gn2 = (lane & 3) << 1;

    if (MODE == 0 && (n0 >> 9) == 2) {
        // V tile: stage transposed in SMEM, copy out coalesced Vt rows.
        __syncthreads();
        #pragma unroll
        for (int mt = 0; mt < 4; mt++)
            #pragma unroll
            for (int nt = 0; nt < 4; nt++)
                #pragma unroll
                for (int hf = 0; hf < 2; hf++) {
                    const int ml = wm * 64 + mt * 16 + gm + hf * 8;
                    const int nl = wn * 32 + nt * 8 + gn2;
                    *reinterpret_cast<__half*>(sm + (uint32_t)nl * 272u + (ml << 1)) =
                        __float2half(acc[mt][nt][hf * 2 + 0]);
                    *reinterpret_cast<__half*>(sm + (uint32_t)(nl + 1) * 272u + (ml << 1)) =
                        __float2half(acc[mt][nt][hf * 2 + 1]);
                }
        __syncthreads();
        const int b = m0 >> 11, t0 = m0 & 2047;
        const int hh0 = (n0 & 511) >> 6;
        #pragma unroll
        for (int i = 0; i < 8; i++) {
            int idx = tid + (i << 8);
            int r = idx >> 4, c16 = idx & 15;
            uint4 v = *reinterpret_cast<const uint4*>(sm + (uint32_t)r * 272u + (c16 << 4));
            int hh = hh0 + (r >> 6), d = r & 63;
            *reinterpret_cast<uint4*>(
                ov + (((size_t)((b << 3) + hh) * 64 + d) * 2048 + t0) + (c16 << 3)) = v;
        }
        return;
    }

    #pragma unroll
    for (int mt = 0; mt < 4; mt++) {
        #pragma unroll
        for (int nt = 0; nt < 4; nt++) {
            #pragma unroll
            for (int hf = 0; hf < 2; hf++) {
                const int m = m0 + wm * 64 + mt * 16 + gm + hf * 8;
                const int n = n0 + wn * 32 + nt * 8 + gn2;
                float v0 = acc[mt][nt][hf * 2 + 0], v1 = acc[mt][nt][hf * 2 + 1];
                if (MODE == 1) {
                    size_t ri = (size_t)m * 512 + n;
                    float2 o = { v0 + bias[n] + res[ri], v1 + bias[n + 1] + res[ri + 1] };
                    *reinterpret_cast<float2*>(outf + ri) = o;
                } else if (MODE == 2) {
                    *reinterpret_cast<uint32_t*>(outh + (size_t)m * 2048 + n) =
                        pack2(fmaxf(v0 + bias[n], 0.f), fmaxf(v1 + bias[n + 1], 0.f));
                } else {
                    int hh = (n & 511) >> 6, d = n & 63;
                    int b = m >> 11, t2 = m & 2047;
                    int bh = (b << 3) + hh;
                    __half* dst = (n >> 9) == 0 ? oq : ok2;
                    *reinterpret_cast<uint32_t*>(dst + ((size_t)bh * 2048 + t2) * 64 + d) =
                        pack2(v0, v1);
                }
            }
        }
    }
}

// ------- score_sum: column-sum partials of exp2(q.k) masked; no S store -----
__global__ __launch_bounds__(256, 2) void score_sum(
    const __half* __restrict__ q, const __half* __restrict__ k,
    float* __restrict__ psum)
{
    extern __shared__ __align__(1024) char sm[];
    const uint32_t sQ = smem_u32(sm);
    const uint32_t sK = sQ + 16384;
    const int tid = threadIdx.x, lane = tid & 31, w = tid >> 5;
    const int wm = w & 1, wn = w >> 1;
    const int tt = (int)gridDim.x - 1 - (int)blockIdx.x, bh = blockIdx.y;
    const __half* qb = q + ((size_t)bh * TS + (size_t)tt * 128) * 64;
    const __half* kb = k + (size_t)bh * TS * 64;

    ld_tile_cp<128>(qb, 64, sQ, tid);
    ld_tile_cp<128>(kb, 64, sK, tid);
    CP_COMMIT();
    if (tt >= 1) {
        ld_tile_cp<128>(kb + 8192, 64, sK + 16384, tid);
        CP_COMMIT();
    }
    const int gm = lane >> 2, gn2 = (lane & 3) << 1;
    for (int st = 0; st <= tt; st++) {
        if (st < tt) cp_wait<1>(); else cp_wait<0>();
        __syncthreads();
        if (st + 2 <= tt) {
            ld_tile_cp<128>(kb + (size_t)(st + 2) * 8192, 64,
                            sK + ((uint32_t)((st + 2) % 3) << 14), tid);
            CP_COMMIT();
        }
        float acc[4][4][4];
        #pragma unroll
        for (int i = 0; i < 4; i++)
            #pragma unroll
            for (int j = 0; j < 4; j++)
                #pragma unroll
                for (int e = 0; e < 4; e++) acc[i][j][e] = 0.f;
        mma_chunk(sQ, sK + ((uint32_t)(st % 3) << 14), lane, wm, wn, acc);
        #pragma unroll
        for (int nt = 0; nt < 4; nt++) {
            float cs0 = 0.f, cs1 = 0.f;
            const int s = st * 128 + wn * 32 + nt * 8 + gn2;
            #pragma unroll
            for (int mt = 0; mt < 4; mt++) {
                #pragma unroll
                for (int hf = 0; hf < 2; hf++) {
                    const int t2 = tt * 128 + wm * 64 + mt * 16 + gm + hf * 8;
                    float e0 = exp2f(acc[mt][nt][hf * 2 + 0]);
                    float e1 = exp2f(acc[mt][nt][hf * 2 + 1]);
                    if (st == tt) {
                        if (s > t2)     e0 = 0.f;
                        if (s + 1 > t2) e1 = 0.f;
                    }
                    cs0 += e0; cs1 += e1;
                }
            }
            #pragma unroll
            for (int o = 4; o < 32; o <<= 1) {
                cs0 += __shfl_xor_sync(~0u, cs0, o);
                cs1 += __shfl_xor_sync(~0u, cs1, o);
            }
            if (lane < 4) {
                float* pm = psum + ((size_t)(tt * 2 + wm) * 32 + bh) * TS + s;
                pm[0] = cs0; pm[1] = cs1;
            }
        }
    }
}

// ---------------- combine column sums -> 1/l ----------------
__global__ __launch_bounds__(256) void combine_sum(
    const float* __restrict__ psum, float* __restrict__ lc)
{
    const int bh = blockIdx.y, s = blockIdx.x * 256 + threadIdx.x;
    const int p0 = (s >> 7) << 1;
    float l = 0.f;
    for (int p = p0; p < 32; p++)
        l += psum[((size_t)p * 32 + bh) * TS + s];
    lc[(size_t)bh * TS + s] = 1.f / l;
}

// ---- pv_fused: E = exp2(QK)*linv in regs, out = E @ Vt^T; no S buffer ------
// 256 threads / 8 warps, 128-row t-blocks (each 64-s chunk feeds 128 rows).
// SMEM: Q 16KB | K 3x8KB | V 3x8KB = 64KB -> 2 CTAs/SM.
__global__ __launch_bounds__(256, 2) void pv_fused(
    const __half* __restrict__ q, const __half* __restrict__ k,
    const __half* __restrict__ Vs, const float* __restrict__ lc,
    __half* __restrict__ ao)
{
    extern __shared__ __align__(1024) char sm[];
    const uint32_t sQ = smem_u32(sm);
    const uint32_t sK = sQ + 16384;
    const uint32_t sV = sK + 24576;
    const int tid = threadIdx.x, lane = tid & 31, wm = tid >> 5;  // 0..7
    const int tb = (int)gridDim.x - 1 - (int)blockIdx.x, bh = blockIdx.y;
    const __half* qb = q + ((size_t)bh * TS + (size_t)tb * 128) * 64;
    const __half* kb = k + (size_t)bh * TS * 64;
    const __half* vb = Vs + (size_t)bh * 64 * TS;
    const float* lcb = lc + (size_t)bh * TS;

    const int nch = 2 * (tb + 1);
    ld_tile_cpN<128, 256>(qb, 64, sQ, tid);
    ld_tile_cpN<64, 256>(kb, 64, sK, tid);
    ld_tile_cpN<64, 256>(vb, TS, sV, tid);
    CP_COMMIT();
    ld_tile_cpN<64, 256>(kb + 4096, 64, sK + 8192, tid);
    ld_tile_cpN<64, 256>(vb + 64, TS, sV + 8192, tid);
    CP_COMMIT();

    float accPV[8][4];
    #pragma unroll
    for (int i = 0; i < 8; i++)
        #pragma unroll
        for (int e = 0; e < 4; e++) accPV[i][e] = 0.f;

    uint32_t qf[4][4];
    const int gm = lane >> 2, gn2 = (lane & 3) << 1;
    const int trow = tb * 128 + wm * 16 + gm;

    for (int c = 0; c < nch; c++) {
        if (c + 1 < nch) cp_wait<1>(); else cp_wait<0>();
        __syncthreads();
        if (c == 0) {      // Q resident now; preload fragments once
            const int row = wm * 16 + (lane & 15);
            #pragma unroll
            for (int ks = 0; ks < 4; ks++) {
                uint32_t koff = (uint32_t)(ks << 5) + ((lane & 16) ? 16u : 0u);
                ldsm4(qf[ks], sQ + sw128((uint32_t)(row << 7) + koff));
            }
        }
        if (c + 2 < nch) {
            const uint32_t st = (uint32_t)((c + 2) % 3) << 13;
            ld_tile_cpN<64, 256>(kb + (size_t)(c + 2) * 4096, 64, sK + st, tid);
            ld_tile_cpN<64, 256>(vb + (c + 2) * 64, TS, sV + st, tid);
            CP_COMMIT();
        }
        const uint32_t kbuf = sK + ((uint32_t)(c % 3) << 13);
        const uint32_t vbuf = sV + ((uint32_t)(c % 3) << 13);
        // linv for this chunk's 64 columns (lane-resident, served by shfl)
        const float f0 = __ldg(lcb + c * 64 + lane);
        const float f1 = __ldg(lcb + c * 64 + 32 + lane);
        // QK: E[16 t x 64 s] per warp
        float accE[8][4];
        #pragma unroll
        for (int i = 0; i < 8; i++)
            #pragma unroll
            for (int e = 0; e < 4; e++) accE[i][e] = 0.f;
        #pragma unroll
        for (int ks = 0; ks < 4; ks++) {
            #pragma unroll
            for (int nb = 0; nb < 4; nb++) {
                uint32_t bk[4];
                ldB16(kbuf, lane, nb * 16, ks, bk);
                mma16816(accE[2 * nb],     qf[ks], &bk[0]);
                mma16816(accE[2 * nb + 1], qf[ks], &bk[2]);
            }
        }
        // exp2 + mask + linv scale
        const int s0 = c * 64;
        const bool maybe_mask = (c >= 2 * tb);
        #pragma unroll
        for (int nt = 0; nt < 8; nt++) {
            const int sl = nt * 8 + gn2;
            const int s = s0 + sl;
            float e0 = exp2f(accE[nt][0]);
            float e1 = exp2f(accE[nt][1]);
            float e2 = exp2f(accE[nt][2]);
            float e3 = exp2f(accE[nt][3]);
            if (maybe_mask) {
                if (s > trow)         e0 = 0.f;
                if (s + 1 > trow)     e1 = 0.f;
                if (s > trow + 8)     e2 = 0.f;
                if (s + 1 > trow + 8) e3 = 0.f;
            }
            const float src = (nt < 4) ? f0 : f1;
            const float la = __shfl_sync(~0u, src, sl & 31);
            const float lb = __shfl_sync(~0u, src, (sl + 1) & 31);
            accE[nt][0] = e0 * la; accE[nt][1] = e1 * lb;
            accE[nt][2] = e2 * la; accE[nt][3] = e3 * lb;
        }
        // PV: A = E (C->A fragment reuse), B = Vs tile [64 d x 64 s]
        #pragma unroll
        for (int ks = 0; ks < 4; ks++) {
            uint32_t ae[4];
            ae[0] = pack2(accE[2 * ks][0],     accE[2 * ks][1]);
            ae[1] = pack2(accE[2 * ks][2],     accE[2 * ks][3]);
            ae[2] = pack2(accE[2 * ks + 1][0], accE[2 * ks + 1][1]);
            ae[3] = pack2(accE[2 * ks + 1][2], accE[2 * ks + 1][3]);
            #pragma unroll
            for (int nb = 0; nb < 4; nb++) {
                uint32_t bv[4];
                ldB16(vbuf, lane, nb * 16, ks, bv);
                mma16816(accPV[2 * nb],     ae, &bv[0]);
                mma16816(accPV[2 * nb + 1], ae, &bv[2]);
            }
        }
    }
    // epilogue: rows trow and trow+8, cols d = 8nt + gn2
    __half* o0 = ao + ((size_t)(bh >> 3) * TS + trow) * 512 + (bh & 7) * 64;
    __half* o1 = o0 + (size_t)8 * 512;
    #pragma unroll
    for (int nt = 0; nt < 8; nt++) {
        *reinterpret_cast<uint32_t*>(o0 + nt * 8 + gn2) = pack2(accPV[nt][0], accPV[nt][1]);
        *reinterpret_cast<uint32_t*>(o1 + nt * 8 + gn2) = pack2(accPV[nt][2], accPV[nt][3]);
    }
}

// ---------------- launcher ----------------
extern "C" void kernel_launch(void* const* d_in, const int* in_sizes, int n_in,
                              void* d_out, int out_size)
{
    const float* x  = (const float*)d_in[0];
    const float* Wq = (const float*)d_in[1];
    const float* Wk = (const float*)d_in[2];
    const float* Wv = (const float*)d_in[3];
    const float* Wo = (const float*)d_in[4];
    const float* bo = (const float*)d_in[5];
    const float* W1 = (const float*)d_in[6];
    const float* b1 = (const float*)d_in[7];
    const float* W2 = (const float*)d_in[8];
    const float* b2 = (const float*)d_in[9];
    const float* g1 = (const float*)d_in[10];
    const float* be1= (const float*)d_in[11];
    const float* g2 = (const float*)d_in[12];
    const float* be2= (const float*)d_in[13];
    float* out = (float*)d_out;

    void* sp = nullptr;
    cudaGetSymbolAddress(&sp, g_s);
    unsigned char* b = (unsigned char*)sp;
    __half* p_h   = (__half*)(b + O_H);
    __half* p_h2  = (__half*)(b + O_H2);
    __half* p_ao  = (__half*)(b + O_AO);
    __half* p_ff  = (__half*)(b + O_FF);
    __half* p_q   = (__half*)(b + O_Q);
    __half* p_k   = (__half*)(b + O_K);
    __half* p_vt  = (__half*)(b + O_VT);
    __half* p_wqkv= (__half*)(b + O_WQKV);
    __half* p_wot = (__half*)(b + O_WOT);
    __half* p_w1t = (__half*)(b + O_W1T);
    __half* p_w2t = (__half*)(b + O_W2T);
    float*  p_l   = (float*)(b + O_L);
    float*  p_x2  = (float*)(b + O_X2);
    float*  p_ps  = (float*)(b + O_PS);

    cudaFuncSetAttribute(gemm_mma<0>, cudaFuncAttributeMaxDynamicSharedMemorySize, 98304);
    cudaFuncSetAttribute(gemm_mma<1>, cudaFuncAttributeMaxDynamicSharedMemorySize, 98304);
    cudaFuncSetAttribute(gemm_mma<2>, cudaFuncAttributeMaxDynamicSharedMemorySize, 98304);
    cudaFuncSetAttribute(score_sum,   cudaFuncAttributeMaxDynamicSharedMemorySize, 65536);
    cudaFuncSetAttribute(pv_fused,    cudaFuncAttributeMaxDynamicSharedMemorySize, 65536);

    dim3 b32(32, 32);
    ln_h<<<8192, 256>>>(x, g1, be1, p_h);
    packqkv<<<dim3(16, 2, 24), b32>>>(Wq, Wk, Wv, p_wqkv);
    tr_all<<<2304, b32>>>(Wo, W1, W2, p_wot, p_w1t, p_w2t);
    gemm_mma<0><<<dim3(12, 64), 256, 98304>>>(p_h, p_wqkv, 512, nullptr, nullptr,
                                              nullptr, nullptr, p_q, p_k, p_vt);
    score_sum<<<dim3(16, 32), 256, 65536>>>(p_q, p_k, p_ps);
    combine_sum<<<dim3(8, 32), 256>>>(p_ps, p_l);
    pv_fused<<<dim3(16, 32), 256, 65536>>>(p_q, p_k, p_vt, p_l, p_ao);
    gemm_mma<1><<<dim3(4, 64), 256, 98304>>>(p_ao, p_wot, 512, bo, x,
                                             p_x2, nullptr, nullptr, nullptr, nullptr);
    ln_h<<<8192, 256>>>(p_x2, g2, be2, p_h2);
    gemm_mma<2><<<dim3(16, 64), 256, 98304>>>(p_h2, p_w1t, 512, b1, nullptr,
                                              nullptr, p_ff, nullptr, nullptr, nullptr);
    gemm_mma<1><<<dim3(4, 64), 256, 98304>>>(p_ff, p_w2t, 2048, b2, p_x2,
                                             out, nullptr, nullptr, nullptr, nullptr);
}

// round 17
// speedup vs baseline: 1.0444x; 1.0444x over previous
#include <cuda_runtime.h>
#include <cuda_fp16.h>
#include <cstdint>
#include <cstddef>

#define TS 2048
#define CE 512
#define DINL __device__ __forceinline__

// ---------------- scratch (bytes) ----------------
constexpr size_t B_ROWC = (size_t)8192 * 512 * 2;
constexpr size_t B_FF   = (size_t)8192 * 2048 * 2;
constexpr size_t B_QKV  = (size_t)32 * 2048 * 64 * 2;
constexpr size_t B_COL  = (size_t)32 * 2048 * 4;
constexpr size_t O_H    = 0;
constexpr size_t O_H2   = O_H   + B_ROWC;
constexpr size_t O_AO   = O_H2  + B_ROWC;
constexpr size_t O_FF   = O_AO  + B_ROWC;
constexpr size_t O_Q    = O_FF  + B_FF;
constexpr size_t O_K    = O_Q   + B_QKV;
constexpr size_t O_VT   = O_K   + B_QKV;
constexpr size_t O_WQKV = O_VT  + B_QKV;
constexpr size_t O_WOT  = O_WQKV + (size_t)1536*512*2;
constexpr size_t O_W1T  = O_WOT  + (size_t)512*512*2;
constexpr size_t O_W2T  = O_W1T  + (size_t)2048*512*2;
constexpr size_t O_L    = O_W2T  + (size_t)512*2048*2;
constexpr size_t O_X2   = O_L   + B_COL;
constexpr size_t O_PS   = O_X2  + (size_t)8192*512*4;          // psum [32][32][2048] f32
constexpr size_t SZ_ALL = O_PS  + (size_t)32*32*2048*4;

__device__ __align__(128) unsigned char g_s[SZ_ALL];

// ---------------- helpers ----------------
DINL uint32_t smem_u32(const void* p) {
    uint32_t a;
    asm("{ .reg .u64 t; cvta.to.shared.u64 t, %1; cvt.u32.u64 %0, t; }" : "=r"(a) : "l"(p));
    return a;
}
DINL uint32_t sw128(uint32_t off) { return off ^ ((off >> 3) & 0x70); }

DINL void cp16(uint32_t s, const void* g) {
    asm volatile("cp.async.cg.shared.global [%0], [%1], 16;" :: "r"(s), "l"(g));
}
#define CP_COMMIT() asm volatile("cp.async.commit_group;" ::: "memory")
template<int N> DINL void cp_wait() {
    asm volatile("cp.async.wait_group %0;" :: "n"(N) : "memory");
}

DINL void ldsm4(uint32_t* r, uint32_t a) {
    asm volatile("ldmatrix.sync.aligned.m8n8.x4.shared.b16 {%0,%1,%2,%3}, [%4];"
        : "=r"(r[0]), "=r"(r[1]), "=r"(r[2]), "=r"(r[3]) : "r"(a));
}
DINL void mma16816(float* d, const uint32_t* a, const uint32_t* b) {
    asm volatile("mma.sync.aligned.m16n8k16.row.col.f32.f16.f16.f32 "
        "{%0,%1,%2,%3},{%4,%5,%6,%7},{%8,%9},{%0,%1,%2,%3};"
        : "+f"(d[0]), "+f"(d[1]), "+f"(d[2]), "+f"(d[3])
        : "r"(a[0]), "r"(a[1]), "r"(a[2]), "r"(a[3]), "r"(b[0]), "r"(b[1]));
}
DINL uint32_t pack2(float a, float b) {
    union { __half2 h; uint32_t u; } cv;
    cv.h = __floats2half2_rn(a, b);
    return cv.u;
}
// async tile copy: NR rows x 64 halves (128B rows), SW128 swizzled; NTH threads
template<int NR, int NTH>
DINL void ld_tile_cpN(const __half* __restrict__ g, int ldh, uint32_t smp, int tid) {
    #pragma unroll
    for (int p = 0; p < NR * 8 / NTH; p++) {
        int u = tid + p * NTH, r = u >> 3, cc = u & 7;
        cp16(smp + sw128((uint32_t)(r << 7) + (cc << 4)),
             g + (size_t)r * ldh + (cc << 3));
    }
}
template<int NR>
DINL void ld_tile_cp(const __half* __restrict__ g, int ldh, uint32_t smp, int tid) {
    ld_tile_cpN<NR, 256>(g, ldh, smp, tid);
}
DINL void ldA(uint32_t buf, int lane, int m0, int ks, uint32_t a[4][4]) {
    int row = m0 + (lane & 15);
    uint32_t koff = (uint32_t)(ks << 5) + ((lane & 16) ? 16u : 0u);
    #pragma unroll
    for (int mt = 0; mt < 4; mt++)
        ldsm4(a[mt], buf + sw128((uint32_t)((row + mt * 16) << 7) + koff));
}
DINL void ldB16(uint32_t buf, int lane, int n0, int ks, uint32_t b[4]) {
    int row = n0 + (lane & 7) + ((lane & 16) >> 1);
    uint32_t koff = (uint32_t)(ks << 5) + ((lane & 8) << 1);
    ldsm4(b, buf + sw128((uint32_t)(row << 7) + koff));
}
// 64-K chunk (warp tile 64x32, 8 warps)
DINL void mma_chunk(uint32_t abuf, uint32_t bbuf, int lane, int wm, int wn, float acc[4][4][4]) {
    #pragma unroll
    for (int ks = 0; ks < 4; ks++) {
        uint32_t a[4][4], b[2][4];
        ldA(abuf, lane, wm * 64, ks, a);
        ldB16(bbuf, lane, wn * 32, ks, b[0]);
        ldB16(bbuf, lane, wn * 32 + 16, ks, b[1]);
        #pragma unroll
        for (int mt = 0; mt < 4; mt++)
            #pragma unroll
            for (int nt = 0; nt < 4; nt++)
                mma16816(acc[mt][nt], a[mt], &b[nt >> 1][(nt & 1) * 2]);
    }
}

// ---------------- LayerNorm fp32 -> fp16 ----------------
__global__ __launch_bounds__(256) void ln_h(
    const float* __restrict__ x, const float* __restrict__ g,
    const float* __restrict__ be, __half* __restrict__ o)
{
    const int row = blockIdx.x, t = threadIdx.x;
    const float* xr = x + (size_t)row * CE;
    float2 ab = *reinterpret_cast<const float2*>(xr + 2 * t);
    float s = ab.x + ab.y, sq = ab.x * ab.x + ab.y * ab.y;
    #pragma unroll
    for (int off = 16; off; off >>= 1) {
        s  += __shfl_xor_sync(~0u, s, off);
        sq += __shfl_xor_sync(~0u, sq, off);
    }
    __shared__ float sh[16];
    if ((t & 31) == 0) { sh[t >> 5] = s; sh[8 + (t >> 5)] = sq; }
    __syncthreads();
    if (t == 0) {
        float S = 0, Q = 0;
        #pragma unroll
        for (int i = 0; i < 8; i++) { S += sh[i]; Q += sh[8 + i]; }
        sh[0] = S; sh[8] = Q;
    }
    __syncthreads();
    float mu = sh[0] * (1.f / 512), var = sh[8] * (1.f / 512) - mu * mu;
    float inv = rsqrtf(var + 1e-5f);
    float o0 = (ab.x - mu) * inv * g[2 * t] + be[2 * t];
    float o1 = (ab.y - mu) * inv * g[2 * t + 1] + be[2 * t + 1];
    *reinterpret_cast<__half2*>(o + (size_t)row * CE + 2 * t) = __floats2half2_rn(o0, o1);
}

// ---------------- weight prep ----------------
__global__ void packqkv(const float* __restrict__ Wq, const float* __restrict__ Wk,
                        const float* __restrict__ Wv, __half* __restrict__ wt)
{
    __shared__ float tl[32][33];
    int c0 = blockIdx.x << 5, d0 = blockIdx.y << 5, z = blockIdx.z;
    int which = z >> 3, h = z & 7;
    const float* W = which == 0 ? Wq : (which == 1 ? Wk : Wv);
    // q scale: 512^-0.5 * log2(e)  (scores use exp2)
    float sc = which == 0 ? 0.04419417382415922f * 1.4426950408889634f : 1.f;
    tl[threadIdx.y][threadIdx.x] =
        W[((size_t)h * 512 + c0 + threadIdx.y) * 64 + d0 + threadIdx.x] * sc;
    __syncthreads();
    wt[((size_t)(which * 512 + h * 64 + d0 + threadIdx.y)) * 512 + c0 + threadIdx.x] =
        __float2half(tl[threadIdx.x][threadIdx.y]);
}
__global__ void tr_all(const float* __restrict__ Wo, const float* __restrict__ W1,
                       const float* __restrict__ W2, __half* __restrict__ wot,
                       __half* __restrict__ w1t, __half* __restrict__ w2t)
{
    __shared__ float tl[32][33];
    int bid = blockIdx.x;
    const float* in; __half* out; int K, N, tx_, ty_;
    if (bid < 256)       { in = Wo; out = wot; K = 512;  N = 512;  bid -= 0;    tx_ = bid & 15; ty_ = bid >> 4; }
    else if (bid < 1280) { in = W1; out = w1t; K = 512;  N = 2048; bid -= 256;  tx_ = bid & 63; ty_ = bid >> 6; }
    else                 { in = W2; out = w2t; K = 2048; N = 512;  bid -= 1280; tx_ = bid & 15; ty_ = bid >> 4; }
    int n0 = tx_ << 5, k0 = ty_ << 5;
    tl[threadIdx.y][threadIdx.x] = in[(size_t)(k0 + threadIdx.y) * N + n0 + threadIdx.x];
    __syncthreads();
    out[(size_t)(n0 + threadIdx.y) * K + k0 + threadIdx.x] = __float2half(tl[threadIdx.x][threadIdx.y]);
}

// ---------------- GEMM (cp.async 3-stage 64-K chunks, 2 CTAs/SM) ------------
template<int MODE>
__global__ __launch_bounds__(256, 2) void gemm_mma(
    const __half* __restrict__ A, const __half* __restrict__ B, int K,
    const float* __restrict__ bias, const float* __restrict__ res,
    float* __restrict__ outf, __half* __restrict__ outh,
    __half* __restrict__ oq, __half* __restrict__ ok2, __half* __restrict__ ov)
{
    extern __shared__ __align__(1024) char sm[];
    const uint32_t sA = smem_u32(sm);
    const uint32_t sB = sA + 49152;
    const int tid = threadIdx.x, lane = tid & 31, w = tid >> 5;
    const int wm = w & 1, wn = w >> 1;
    const int m0 = blockIdx.y << 7, n0 = blockIdx.x << 7;
    const __half* Ab = A + (size_t)m0 * K;
    const __half* Bb = B + (size_t)n0 * K;
    float acc[4][4][4];
    #pragma unroll
    for (int i = 0; i < 4; i++)
        #pragma unroll
        for (int j = 0; j < 4; j++)
            #pragma unroll
            for (int e = 0; e < 4; e++) acc[i][j][e] = 0.f;

    const int nc = K >> 6;
    ld_tile_cp<128>(Ab, K, sA, tid);
    ld_tile_cp<128>(Bb, K, sB, tid);
    CP_COMMIT();
    if (nc > 1) {
        ld_tile_cp<128>(Ab + 64, K, sA + 16384, tid);
        ld_tile_cp<128>(Bb + 64, K, sB + 16384, tid);
        CP_COMMIT();
    }
    for (int c = 0; c < nc; c++) {
        if (c + 1 < nc) cp_wait<1>(); else cp_wait<0>();
        __syncthreads();
        if (c + 2 < nc) {
            const uint32_t st = (uint32_t)((c + 2) % 3) << 14;
            ld_tile_cp<128>(Ab + ((c + 2) << 6), K, sA + st, tid);
            ld_tile_cp<128>(Bb + ((c + 2) << 6), K, sB + st, tid);
            CP_COMMIT();
        }
        const uint32_t cur = (uint32_t)(c % 3) << 14;
        mma_chunk(sA + cur, sB + cur, lane, wm, wn, acc);
    }
    const int gm = lane >> 2, gn2 = (lane & 3) << 1;

    if (MODE == 0 && (n0 >> 9) == 2) {
        // V tile: stage transposed in SMEM, copy out coalesced Vt rows.
        __syncthreads();
        #pragma unroll
        for (int mt = 0; mt < 4; mt++)
            #pragma unroll
            for (int nt = 0; nt < 4; nt++)
                #pragma unroll
                for (int hf = 0; hf < 2; hf++) {
                    const int ml = wm * 64 + mt * 16 + gm + hf * 8;
                    const int nl = wn * 32 + nt * 8 + gn2;
                    *reinterpret_cast<__half*>(sm + (uint32_t)nl * 272u + (ml << 1)) =
                        __float2half(acc[mt][nt][hf * 2 + 0]);
                    *reinterpret_cast<__half*>(sm + (uint32_t)(nl + 1) * 272u + (ml << 1)) =
                        __float2half(acc[mt][nt][hf * 2 + 1]);
                }
        __syncthreads();
        const int b = m0 >> 11, t0 = m0 & 2047;
        const int hh0 = (n0 & 511) >> 6;
        #pragma unroll
        for (int i = 0; i < 8; i++) {
            int idx = tid + (i << 8);
            int r = idx >> 4, c16 = idx & 15;
            uint4 v = *reinterpret_cast<const uint4*>(sm + (uint32_t)r * 272u + (c16 << 4));
            int hh = hh0 + (r >> 6), d = r & 63;
            *reinterpret_cast<uint4*>(
                ov + (((size_t)((b << 3) + hh) * 64 + d) * 2048 + t0) + (c16 << 3)) = v;
        }
        return;
    }

    #pragma unroll
    for (int mt = 0; mt < 4; mt++) {
        #pragma unroll
        for (int nt = 0; nt < 4; nt++) {
            #pragma unroll
            for (int hf = 0; hf < 2; hf++) {
                const int m = m0 + wm * 64 + mt * 16 + gm + hf * 8;
                const int n = n0 + wn * 32 + nt * 8 + gn2;
                float v0 = acc[mt][nt][hf * 2 + 0], v1 = acc[mt][nt][hf * 2 + 1];
                if (MODE == 1) {
                    size_t ri = (size_t)m * 512 + n;
                    float2 o = { v0 + bias[n] + res[ri], v1 + bias[n + 1] + res[ri + 1] };
                    *reinterpret_cast<float2*>(outf + ri) = o;
                } else if (MODE == 2) {
                    *reinterpret_cast<uint32_t*>(outh + (size_t)m * 2048 + n) =
                        pack2(fmaxf(v0 + bias[n], 0.f), fmaxf(v1 + bias[n + 1], 0.f));
                } else {
                    int hh = (n & 511) >> 6, d = n & 63;
                    int b = m >> 11, t2 = m & 2047;
                    int bh = (b << 3) + hh;
                    __half* dst = (n >> 9) == 0 ? oq : ok2;
                    *reinterpret_cast<uint32_t*>(dst + ((size_t)bh * 2048 + t2) * 64 + d) =
                        pack2(v0, v1);
                }
            }
        }
    }
}

// ------- score_sum: column-sum partials of exp2(q.k) masked; no S store -----
__global__ __launch_bounds__(256, 2) void score_sum(
    const __half* __restrict__ q, const __half* __restrict__ k,
    float* __restrict__ psum)
{
    extern __shared__ __align__(1024) char sm[];
    const uint32_t sQ = smem_u32(sm);
    const uint32_t sK = sQ + 16384;
    const int tid = threadIdx.x, lane = tid & 31, w = tid >> 5;
    const int wm = w & 1, wn = w >> 1;
    const int tt = (int)gridDim.x - 1 - (int)blockIdx.x, bh = blockIdx.y;
    const __half* qb = q + ((size_t)bh * TS + (size_t)tt * 128) * 64;
    const __half* kb = k + (size_t)bh * TS * 64;

    ld_tile_cp<128>(qb, 64, sQ, tid);
    ld_tile_cp<128>(kb, 64, sK, tid);
    CP_COMMIT();
    if (tt >= 1) {
        ld_tile_cp<128>(kb + 8192, 64, sK + 16384, tid);
        CP_COMMIT();
    }
    const int gm = lane >> 2, gn2 = (lane & 3) << 1;
    for (int st = 0; st <= tt; st++) {
        if (st < tt) cp_wait<1>(); else cp_wait<0>();
        __syncthreads();
        if (st + 2 <= tt) {
            ld_tile_cp<128>(kb + (size_t)(st + 2) * 8192, 64,
                            sK + ((uint32_t)((st + 2) % 3) << 14), tid);
            CP_COMMIT();
        }
        float acc[4][4][4];
        #pragma unroll
        for (int i = 0; i < 4; i++)
            #pragma unroll
            for (int j = 0; j < 4; j++)
                #pragma unroll
                for (int e = 0; e < 4; e++) acc[i][j][e] = 0.f;
        mma_chunk(sQ, sK + ((uint32_t)(st % 3) << 14), lane, wm, wn, acc);
        #pragma unroll
        for (int nt = 0; nt < 4; nt++) {
            float cs0 = 0.f, cs1 = 0.f;
            const int s = st * 128 + wn * 32 + nt * 8 + gn2;
            #pragma unroll
            for (int mt = 0; mt < 4; mt++) {
                #pragma unroll
                for (int hf = 0; hf < 2; hf++) {
                    const int t2 = tt * 128 + wm * 64 + mt * 16 + gm + hf * 8;
                    float e0 = exp2f(acc[mt][nt][hf * 2 + 0]);
                    float e1 = exp2f(acc[mt][nt][hf * 2 + 1]);
                    if (st == tt) {
                        if (s > t2)     e0 = 0.f;
                        if (s + 1 > t2) e1 = 0.f;
                    }
                    cs0 += e0; cs1 += e1;
                }
            }
            #pragma unroll
            for (int o = 4; o < 32; o <<= 1) {
                cs0 += __shfl_xor_sync(~0u, cs0, o);
                cs1 += __shfl_xor_sync(~0u, cs1, o);
            }
            if (lane < 4) {
                float* pm = psum + ((size_t)(tt * 2 + wm) * 32 + bh) * TS + s;
                pm[0] = cs0; pm[1] = cs1;
            }
        }
    }
}

// ---------------- combine column sums -> 1/l ----------------
__global__ __launch_bounds__(256) void combine_sum(
    const float* __restrict__ psum, float* __restrict__ lc)
{
    const int bh = blockIdx.y, s = blockIdx.x * 256 + threadIdx.x;
    const int p0 = (s >> 7) << 1;
    float l = 0.f;
    for (int p = p0; p < 32; p++)
        l += psum[((size_t)p * 32 + bh) * TS + s];
    lc[(size_t)bh * TS + s] = 1.f / l;
}

// ---------------- fold linv into Vt rows (in place) ----------------
__global__ __launch_bounds__(256) void scale_v(
    __half* __restrict__ vt, const float* __restrict__ lc)
{
    const int row = blockIdx.x;           // bh*64 + d
    const int bh = row >> 6;
    __half2* vp = reinterpret_cast<__half2*>(vt + (size_t)row * TS);
    const float2* lp = reinterpret_cast<const float2*>(lc + (size_t)bh * TS);
    #pragma unroll
    for (int i = threadIdx.x; i < 1024; i += 256) {
        float2 l = lp[i];
        float2 v = __half22float2(vp[i]);
        vp[i] = __floats2half2_rn(v.x * l.x, v.y * l.y);
    }
}

// ---- pv_fused: E = exp2(QK) in regs, out = E @ Vs^T; no S buffer -----------
// 128 threads (4 warps), each warp owns 16 t-rows. 64-row t-blocks.
// SMEM: Q 8KB | K 3x8KB | V 3x8KB = 56KB -> 4 CTAs/SM.
__global__ __launch_bounds__(128, 4) void pv_fused(
    const __half* __restrict__ q, const __half* __restrict__ k,
    const __half* __restrict__ Vs, __half* __restrict__ ao)
{
    extern __shared__ __align__(1024) char sm[];
    const uint32_t sQ = smem_u32(sm);
    const uint32_t sK = sQ + 8192;
    const uint32_t sV = sK + 24576;
    const int tid = threadIdx.x, lane = tid & 31, wm = tid >> 5;  // 0..3
    const int tb = (int)gridDim.x - 1 - (int)blockIdx.x, bh = blockIdx.y;
    const __half* qb = q + ((size_t)bh * TS + (size_t)tb * 64) * 64;
    const __half* kb = k + (size_t)bh * TS * 64;
    const __half* vb = Vs + (size_t)bh * 64 * TS;

    const int nch = tb + 1;
    ld_tile_cpN<64, 128>(qb, 64, sQ, tid);
    ld_tile_cpN<64, 128>(kb, 64, sK, tid);
    ld_tile_cpN<64, 128>(vb, TS, sV, tid);
    CP_COMMIT();
    if (nch > 1) {
        ld_tile_cpN<64, 128>(kb + 4096, 64, sK + 8192, tid);
        ld_tile_cpN<64, 128>(vb + 64, TS, sV + 8192, tid);
        CP_COMMIT();
    }

    float accPV[8][4];
    #pragma unroll
    for (int i = 0; i < 8; i++)
        #pragma unroll
        for (int e = 0; e < 4; e++) accPV[i][e] = 0.f;

    uint32_t qf[4][4];
    const int gm = lane >> 2, gn2 = (lane & 3) << 1;
    const int trow = tb * 64 + wm * 16 + gm;

    for (int c = 0; c < nch; c++) {
        if (c + 1 < nch) cp_wait<1>(); else cp_wait<0>();
        __syncthreads();
        if (c == 0) {      // Q resident now; preload fragments once
            const int row = wm * 16 + (lane & 15);
            #pragma unroll
            for (int ks = 0; ks < 4; ks++) {
                uint32_t koff = (uint32_t)(ks << 5) + ((lane & 16) ? 16u : 0u);
                ldsm4(qf[ks], sQ + sw128((uint32_t)(row << 7) + koff));
            }
        }
        if (c + 2 < nch) {
            const uint32_t st = (uint32_t)((c + 2) % 3) << 13;
            ld_tile_cpN<64, 128>(kb + (size_t)(c + 2) * 4096, 64, sK + st, tid);
            ld_tile_cpN<64, 128>(vb + (c + 2) * 64, TS, sV + st, tid);
            CP_COMMIT();
        }
        const uint32_t kbuf = sK + ((uint32_t)(c % 3) << 13);
        const uint32_t vbuf = sV + ((uint32_t)(c % 3) << 13);
        // QK: E[16 t x 64 s] per warp
        float accE[8][4];
        #pragma unroll
        for (int i = 0; i < 8; i++)
            #pragma unroll
            for (int e = 0; e < 4; e++) accE[i][e] = 0.f;
        #pragma unroll
        for (int ks = 0; ks < 4; ks++) {
            #pragma unroll
            for (int nb = 0; nb < 4; nb++) {
                uint32_t bk[4];
                ldB16(kbuf, lane, nb * 16, ks, bk);
                mma16816(accE[2 * nb],     qf[ks], &bk[0]);
                mma16816(accE[2 * nb + 1], qf[ks], &bk[2]);
            }
        }
        // exp2 + mask (only the diagonal chunk needs masking)
        const int s0 = c * 64;
        const bool diag = (c == tb);
        #pragma unroll
        for (int nt = 0; nt < 8; nt++) {
            const int s = s0 + nt * 8 + gn2;
            float e0 = exp2f(accE[nt][0]);
            float e1 = exp2f(accE[nt][1]);
            float e2 = exp2f(accE[nt][2]);
            float e3 = exp2f(accE[nt][3]);
            if (diag) {
                if (s > trow)         e0 = 0.f;
                if (s + 1 > trow)     e1 = 0.f;
                if (s > trow + 8)     e2 = 0.f;
                if (s + 1 > trow + 8) e3 = 0.f;
            }
            accE[nt][0] = e0; accE[nt][1] = e1; accE[nt][2] = e2; accE[nt][3] = e3;
        }
        // PV: A = E (C->A fragment reuse), B = Vs tile [64 d x 64 s]
        #pragma unroll
        for (int ks = 0; ks < 4; ks++) {
            uint32_t ae[4];
            ae[0] = pack2(accE[2 * ks][0],     accE[2 * ks][1]);
            ae[1] = pack2(accE[2 * ks][2],     accE[2 * ks][3]);
            ae[2] = pack2(accE[2 * ks + 1][0], accE[2 * ks + 1][1]);
            ae[3] = pack2(accE[2 * ks + 1][2], accE[2 * ks + 1][3]);
            #pragma unroll
            for (int nb = 0; nb < 4; nb++) {
                uint32_t bv[4];
                ldB16(vbuf, lane, nb * 16, ks, bv);
                mma16816(accPV[2 * nb],     ae, &bv[0]);
                mma16816(accPV[2 * nb + 1], ae, &bv[2]);
            }
        }
    }
    // epilogue: rows trow and trow+8, cols d = 8nt + gn2
    __half* o0 = ao + ((size_t)(bh >> 3) * TS + trow) * 512 + (bh & 7) * 64;
    __half* o1 = o0 + (size_t)8 * 512;
    #pragma unroll
    for (int nt = 0; nt < 8; nt++) {
        *reinterpret_cast<uint32_t*>(o0 + nt * 8 + gn2) = pack2(accPV[nt][0], accPV[nt][1]);
        *reinterpret_cast<uint32_t*>(o1 + nt * 8 + gn2) = pack2(accPV[nt][2], accPV[nt][3]);
    }
}

// ---------------- launcher ----------------
extern "C" void kernel_launch(void* const* d_in, const int* in_sizes, int n_in,
                              void* d_out, int out_size)
{
    const float* x  = (const float*)d_in[0];
    const float* Wq = (const float*)d_in[1];
    const float* Wk = (const float*)d_in[2];
    const float* Wv = (const float*)d_in[3];
    const float* Wo = (const float*)d_in[4];
    const float* bo = (const float*)d_in[5];
    const float* W1 = (const float*)d_in[6];
    const float* b1 = (const float*)d_in[7];
    const float* W2 = (const float*)d_in[8];
    const float* b2 = (const float*)d_in[9];
    const float* g1 = (const float*)d_in[10];
    const float* be1= (const float*)d_in[11];
    const float* g2 = (const float*)d_in[12];
    const float* be2= (const float*)d_in[13];
    float* out = (float*)d_out;

    void* sp = nullptr;
    cudaGetSymbolAddress(&sp, g_s);
    unsigned char* b = (unsigned char*)sp;
    __half* p_h   = (__half*)(b + O_H);
    __half* p_h2  = (__half*)(b + O_H2);
    __half* p_ao  = (__half*)(b + O_AO);
    __half* p_ff  = (__half*)(b + O_FF);
    __half* p_q   = (__half*)(b + O_Q);
    __half* p_k   = (__half*)(b + O_K);
    __half* p_vt  = (__half*)(b + O_VT);
    __half* p_wqkv= (__half*)(b + O_WQKV);
    __half* p_wot = (__half*)(b + O_WOT);
    __half* p_w1t = (__half*)(b + O_W1T);
    __half* p_w2t = (__half*)(b + O_W2T);
    float*  p_l   = (float*)(b + O_L);
    float*  p_x2  = (float*)(b + O_X2);
    float*  p_ps  = (float*)(b + O_PS);

    cudaFuncSetAttribute(gemm_mma<0>, cudaFuncAttributeMaxDynamicSharedMemorySize, 98304);
    cudaFuncSetAttribute(gemm_mma<1>, cudaFuncAttributeMaxDynamicSharedMemorySize, 98304);
    cudaFuncSetAttribute(gemm_mma<2>, cudaFuncAttributeMaxDynamicSharedMemorySize, 98304);
    cudaFuncSetAttribute(score_sum,   cudaFuncAttributeMaxDynamicSharedMemorySize, 65536);
    cudaFuncSetAttribute(pv_fused,    cudaFuncAttributeMaxDynamicSharedMemorySize, 57344);

    dim3 b32(32, 32);
    ln_h<<<8192, 256>>>(x, g1, be1, p_h);
    packqkv<<<dim3(16, 2, 24), b32>>>(Wq, Wk, Wv, p_wqkv);
    tr_all<<<2304, b32>>>(Wo, W1, W2, p_wot, p_w1t, p_w2t);
    gemm_mma<0><<<dim3(12, 64), 256, 98304>>>(p_h, p_wqkv, 512, nullptr, nullptr,
                                              nullptr, nullptr, p_q, p_k, p_vt);
    score_sum<<<dim3(16, 32), 256, 65536>>>(p_q, p_k, p_ps);
    combine_sum<<<dim3(8, 32), 256>>>(p_ps, p_l);
    scale_v<<<2048, 256>>>(p_vt, p_l);
    pv_fused<<<dim3(32, 32), 128, 57344>>>(p_q, p_k, p_vt, p_ao);
    gemm_mma<1><<<dim3(4, 64), 256, 98304>>>(p_ao, p_wot, 512, bo, x,
                                             p_x2, nullptr, nullptr, nullptr, nullptr);
    ln_h<<<8192, 256>>>(p_x2, g2, be2, p_h2);
    gemm_mma<2><<<dim3(16, 64), 256, 98304>>>(p_h2, p_w1t, 512, b1, nullptr,
                                              nullptr, p_ff, nullptr, nullptr, nullptr);
    gemm_mma<1><<<dim3(4, 64), 256, 98304>>>(p_ff, p_w2t, 2048, b2, p_x2,
                                             out, nullptr, nullptr, nullptr, nullptr);
}